// round 5
// baseline (speedup 1.0000x reference)
#include <cuda_runtime.h>

// MinHashSketch: sketch[s][h] = min over nodes m in segment s of dot(x[m], H[h]),
// empty segments -> 0.   x:[500000,256] f32, batch:[500000] int64(or int32, detected),
// H:[128,256] f32, out:[512,128] f32.
//
// GEMM via mma.sync m16n8k8 tf32 (inputs rounded with cvt.rna -> unbiased ~2e-4 err),
// fused segment-min epilogue with order-preserving uint encoding + atomicMin.

#define NODES 500000
#define FDIM 256
#define NH   128
#define NSEG 512

#define BM   128
#define BK   32
#define NBK  (FDIM / BK)        // 8
#define NKT  (FDIM / 8)         // 32 global k-steps
#define NMT  (BM / 16)          // 8 m-tiles
#define NNT  (NH / 8)           // 16 n-tiles
#define THREADS 256

// Shared layout (bytes):
//  Bfrag: 16 nt * (32 ksteps * 66 words) * 4B = 135168   (ksg stride 66 words: bank de-conflict)
//  Afrag: 2 bufs * (32 (mt*4+ks) * 132 words) * 4B = 33792 (132-word stride: bank de-conflict)
//  segs : 128 * 4B
#define B_NT_STRIDE 2112        // words per n-tile (32 * 66)
#define B_KS_STRIDE 66
#define A_STRIDE    132
#define A_BUF_WORDS 4224        // 32 * 132
#define SM_B_WORDS  33792       // 16 * 2112
#define SM_A_OFF    SM_B_WORDS
#define SM_SEG_OFF  (SM_B_WORDS + 2 * A_BUF_WORDS)
#define SMEM_BYTES  ((SM_SEG_OFF + 128) * 4)

__device__ int g_is64;

__device__ __forceinline__ unsigned fenc(float f) {
    unsigned u = __float_as_uint(f);
    return (u & 0x80000000u) ? ~u : (u | 0x80000000u);
}

__device__ __forceinline__ unsigned cvt_rna_tf32(float f) {
    unsigned t;
    asm("cvt.rna.tf32.f32 %0, %1;" : "=r"(t) : "f"(f));
    return t;
}

__device__ __forceinline__ void mma8(float* c, const unsigned* a, const unsigned* b) {
    asm volatile(
        "mma.sync.aligned.m16n8k8.row.col.f32.tf32.tf32.f32 "
        "{%0,%1,%2,%3}, {%4,%5,%6,%7}, {%8,%9}, {%0,%1,%2,%3};"
        : "+f"(c[0]), "+f"(c[1]), "+f"(c[2]), "+f"(c[3])
        : "r"(a[0]), "r"(a[1]), "r"(a[2]), "r"(a[3]), "r"(b[0]), "r"(b[1]));
}

__global__ void init_kernel(unsigned* outu) {
    int i = blockIdx.x * blockDim.x + threadIdx.x;
    if (i < NSEG * NH) outu[i] = 0xFFFFFFFFu;
    if (i == 0) g_is64 = 1;
}

// batch dtype sniffing: if int64, odd int32 words are hi-words == 0 (values in [0,512)).
// If int32, sorted values > 0 occupy odd indices past the first segment -> some nonzero.
__global__ void detect_kernel(const int* b) {
    int idx = blockIdx.x * blockDim.x + threadIdx.x;
    int i = idx * 2 + 1;
    if (i < NODES && b[i] != 0) g_is64 = 0;
}

__global__ void decode_kernel(float* out) {
    int i = blockIdx.x * blockDim.x + threadIdx.x;
    if (i < NSEG * NH) {
        unsigned u = __float_as_uint(out[i]);
        float f;
        if (u == 0xFFFFFFFFu) f = 0.0f;  // empty segment -> 0 (reference semantics)
        else f = (u & 0x80000000u) ? __uint_as_float(u ^ 0x80000000u) : __uint_as_float(~u);
        out[i] = f;
    }
}

// ---- A tile helpers: global [128 x BK] slab -> fragment-ready smem layout ----
__device__ __forceinline__ void loadA(float4* areg, const float* __restrict__ x,
                                      int m0, int k0, int tid) {
#pragma unroll
    for (int t = 0; t < 4; t++) {
        int idx = tid + t * THREADS;        // float4 index in 128x32 tile
        int row = idx >> 3;
        int kin = (idx & 7) << 2;
        int m = m0 + row;
        if (m < NODES)
            areg[t] = *(const float4*)(x + (size_t)m * FDIM + (k0 + kin));
        else
            areg[t] = make_float4(0.f, 0.f, 0.f, 0.f);
    }
}

__device__ __forceinline__ void storeA(const float4* areg, float* Af, int buf, int tid) {
    float* base = Af + buf * A_BUF_WORDS;
#pragma unroll
    for (int t = 0; t < 4; t++) {
        int idx = tid + t * THREADS;
        int row = idx >> 3;
        int kin = (idx & 7) << 2;
        int mt = row >> 4, rr = row & 15;
        float vv[4] = {areg[t].x, areg[t].y, areg[t].z, areg[t].w};
#pragma unroll
        for (int j = 0; j < 4; j++) {
            int kk = kin + j;               // 0..31 within BK
            int ks = kk >> 3;
            int col = kk & 7;
            int ln = ((rr & 7) << 2) | (col & 3);
            int r = (rr >> 3) | ((col >> 2) << 1);
            base[(mt * 4 + ks) * A_STRIDE + ln * 4 + r] =
                __uint_as_float(cvt_rna_tf32(vv[j]));
        }
    }
}

__global__ void __launch_bounds__(THREADS, 1)
mm_kernel(const float* __restrict__ x, const void* __restrict__ batch_raw,
          const float* __restrict__ H, unsigned* __restrict__ outu) {
    extern __shared__ float sm[];
    float* Bf = sm;
    float* Af = sm + SM_A_OFF;
    int* segs = (int*)(sm + SM_SEG_OFF);

    const int tid = threadIdx.x;
    const int m0 = blockIdx.x * BM;
    const int wid = tid >> 5, lane = tid & 31;
    const int wm = wid >> 1, wn = wid & 1;   // 4 (m) x 2 (n) warp grid

    // segment ids for this block's rows
    if (tid < BM) {
        int m = m0 + tid, s = -1;
        if (m < NODES)
            s = g_is64 ? (int)((const long long*)batch_raw)[m]
                       : ((const int*)batch_raw)[m];
        segs[tid] = s;
    }

    // Stage ALL of H into fragment-ready smem (once per block, L2-resident source).
    for (int i = tid; i < (NH * FDIM) / 4; i += THREADS) {
        int base = i * 4;
        int n = base / FDIM;
        int k = base % FDIM;
        float4 v = ((const float4*)H)[i];
        float vv[4] = {v.x, v.y, v.z, v.w};
#pragma unroll
        for (int j = 0; j < 4; j++) {
            int kk = k + j;
            int nt = n >> 3;
            int ksg = kk >> 3;
            int ln = ((n & 7) << 2) | (kk & 3);
            int slot = (kk >> 2) & 1;
            Bf[nt * B_NT_STRIDE + ksg * B_KS_STRIDE + ln * 2 + slot] =
                __uint_as_float(cvt_rna_tf32(vv[j]));
        }
    }

    float acc[2][8][4];
#pragma unroll
    for (int i = 0; i < 2; i++)
#pragma unroll
        for (int j = 0; j < 8; j++)
#pragma unroll
            for (int r = 0; r < 4; r++) acc[i][j][r] = 0.f;

    // prologue: first A slab
    float4 areg[4];
    loadA(areg, x, m0, 0, tid);
    storeA(areg, Af, 0, tid);
    __syncthreads();

#pragma unroll 1
    for (int bk = 0; bk < NBK; bk++) {
        float4 nreg[4];
        if (bk + 1 < NBK) loadA(nreg, x, m0, (bk + 1) * BK, tid);

        const float* Ab = Af + (bk & 1) * A_BUF_WORDS;
#pragma unroll
        for (int ks = 0; ks < 4; ks++) {
            int ksg = bk * 4 + ks;
            unsigned a[2][4], b[8][2];
#pragma unroll
            for (int i = 0; i < 2; i++) {
                int mt = wm * 2 + i;
                float4 av = *(const float4*)(Ab + (mt * 4 + ks) * A_STRIDE + lane * 4);
                a[i][0] = __float_as_uint(av.x); a[i][1] = __float_as_uint(av.y);
                a[i][2] = __float_as_uint(av.z); a[i][3] = __float_as_uint(av.w);
            }
#pragma unroll
            for (int j = 0; j < 8; j++) {
                int nt = wn * 8 + j;
                float2 bv = *(const float2*)(Bf + nt * B_NT_STRIDE + ksg * B_KS_STRIDE + lane * 2);
                b[j][0] = __float_as_uint(bv.x); b[j][1] = __float_as_uint(bv.y);
            }
#pragma unroll
            for (int i = 0; i < 2; i++)
#pragma unroll
                for (int j = 0; j < 8; j++)
                    mma8(acc[i][j], a[i], b[j]);
        }

        if (bk + 1 < NBK) {
            storeA(nreg, Af, (bk + 1) & 1, tid);  // writes the buffer everyone finished reading
            __syncthreads();
        }
    }

    // ---- fused segment-min epilogue ----
    bool full = (m0 + BM) <= NODES;
    int segFirst = segs[0];
    bool fast = full && (segFirst == segs[BM - 1]) && (segFirst >= 0);

    if (fast) {
        // whole block is one segment: shuffle-reduce column mins, 1 atomic per (col, m-warp)
#pragma unroll
        for (int j = 0; j < 8; j++) {
            float v0 = fminf(fminf(acc[0][j][0], acc[0][j][2]), fminf(acc[1][j][0], acc[1][j][2]));
            float v1 = fminf(fminf(acc[0][j][1], acc[0][j][3]), fminf(acc[1][j][1], acc[1][j][3]));
#pragma unroll
            for (int off = 4; off < 32; off <<= 1) {
                v0 = fminf(v0, __shfl_xor_sync(0xffffffffu, v0, off));
                v1 = fminf(v1, __shfl_xor_sync(0xffffffffu, v1, off));
            }
            if (lane < 4) {
                int col = wn * 64 + j * 8 + lane * 2;
                atomicMin(&outu[segFirst * NH + col], fenc(v0));
                atomicMin(&outu[segFirst * NH + col + 1], fenc(v1));
            }
        }
    } else {
        // boundary / tail block: per-element atomicMin (rare: ~13% of blocks)
#pragma unroll
        for (int i = 0; i < 2; i++) {
            int rbase = wm * 32 + i * 16 + (lane >> 2);
#pragma unroll
            for (int j = 0; j < 8; j++) {
                int col = wn * 64 + j * 8 + ((lane & 3) << 1);
#pragma unroll
                for (int h = 0; h < 2; h++) {
                    int rl = rbase + h * 8;
                    if (m0 + rl < NODES) {
                        int s = segs[rl];
                        atomicMin(&outu[s * NH + col],     fenc(acc[i][j][h * 2 + 0]));
                        atomicMin(&outu[s * NH + col + 1], fenc(acc[i][j][h * 2 + 1]));
                    }
                }
            }
        }
    }
}

extern "C" void kernel_launch(void* const* d_in, const int* in_sizes, int n_in,
                              void* d_out, int out_size) {
    const float* x = nullptr;
    const void* batch = nullptr;
    const float* H = nullptr;
    for (int i = 0; i < n_in; i++) {
        int s = in_sizes[i];
        if (s == NODES * FDIM) x = (const float*)d_in[i];
        else if (s == NODES) batch = d_in[i];
        else if (s == NH * FDIM) H = (const float*)d_in[i];
        // a size-1 num_segments scalar, if present, is ignored (compile-time 512)
    }
    unsigned* outu = (unsigned*)d_out;

    cudaFuncSetAttribute(mm_kernel, cudaFuncAttributeMaxDynamicSharedMemorySize, SMEM_BYTES);

    init_kernel<<<(NSEG * NH + 255) / 256, 256>>>(outu);
    detect_kernel<<<(NODES / 2 + 255) / 256, 256>>>((const int*)batch);
    mm_kernel<<<(NODES + BM - 1) / BM, THREADS, SMEM_BYTES>>>(x, batch, H, outu);
    decode_kernel<<<(NSEG * NH + 255) / 256, 256>>>((float*)d_out);
}

// round 9
// speedup vs baseline: 1.4471x; 1.4471x over previous
#include <cuda_runtime.h>
#include <cstdint>

// MinHashSketch: sketch[s][h] = min over nodes m in segment s of dot(x[m], H[h]),
// empty segments -> 0.  x:[500000,256] f32, batch:[500000] i64/i32 (detected),
// H:[128,256] f32, out:[512,128] f32.
//
// Persistent mma.sync m16n8k8 tf32 GEMM (cvt.rna inputs, ~1e-4 err), H staged
// in fragment layout ONCE per CTA, fused segment-min epilogue with
// order-preserving uint encoding + atomicMin.

#define NODES 500000
#define FDIM 256
#define NH   128
#define NSEG 512

#define BM   128
#define BK   32
#define NBK  (FDIM / BK)        // 8
#define THREADS 256
#define NTILES ((NODES + BM - 1) / BM)   // 3907

// Shared layout (words):
//  Bf: 8 nt-pairs * 32 ksg * 132 words = 33792  (paired-fragment layout, LDS.128)
//  Af: 2 bufs * 32 (mt*4+ks) * 132 words = 8448
//  segs: 128, is64: 1
#define B_PAIR_STRIDE 4224      // 32 * 132
#define B_KS_STRIDE   132
#define A_STRIDE      132
#define A_BUF_WORDS   4224
#define SM_B_WORDS    33792
#define SM_A_OFF      SM_B_WORDS
#define SM_SEG_OFF    (SM_B_WORDS + 2 * A_BUF_WORDS)    // 42240
#define SM_IS64_OFF   (SM_SEG_OFF + 128)
#define SMEM_BYTES    ((SM_IS64_OFF + 4) * 4)

__device__ __forceinline__ unsigned fenc(float f) {
    unsigned u = __float_as_uint(f);
    return (u & 0x80000000u) ? ~u : (u | 0x80000000u);
}

__device__ __forceinline__ unsigned cvt_rna_tf32(float f) {
    unsigned t;
    asm("cvt.rna.tf32.f32 %0, %1;" : "=r"(t) : "f"(f));
    return t;
}

__device__ __forceinline__ void mma8(float* c, const unsigned* a, const unsigned* b) {
    asm volatile(
        "mma.sync.aligned.m16n8k8.row.col.f32.tf32.tf32.f32 "
        "{%0,%1,%2,%3}, {%4,%5,%6,%7}, {%8,%9}, {%0,%1,%2,%3};"
        : "+f"(c[0]), "+f"(c[1]), "+f"(c[2]), "+f"(c[3])
        : "r"(a[0]), "r"(a[1]), "r"(a[2]), "r"(a[3]), "r"(b[0]), "r"(b[1]));
}

__global__ void init_kernel(unsigned* outu) {
    int i = blockIdx.x * blockDim.x + threadIdx.x;
    if (i < NSEG * NH) outu[i] = 0xFFFFFFFFu;
}

__global__ void decode_kernel(float* out) {
    int i = blockIdx.x * blockDim.x + threadIdx.x;
    if (i < NSEG * NH) {
        unsigned u = __float_as_uint(out[i]);
        float f;
        if (u == 0xFFFFFFFFu) f = 0.0f;   // empty segment -> 0
        else f = (u & 0x80000000u) ? __uint_as_float(u ^ 0x80000000u) : __uint_as_float(~u);
        out[i] = f;
    }
}

// ---- A tile helpers: global [128 x BK] slab -> fragment-ready smem layout ----
__device__ __forceinline__ void loadA(float4* areg, const float* __restrict__ x,
                                      int m0, int k0, int tid) {
#pragma unroll
    for (int t = 0; t < 4; t++) {
        int idx = tid + t * THREADS;        // float4 index in 128x32 tile
        int row = idx >> 3;
        int kin = (idx & 7) << 2;
        int m = m0 + row;
        if (m < NODES)
            areg[t] = *(const float4*)(x + (size_t)m * FDIM + (k0 + kin));
        else
            areg[t] = make_float4(0.f, 0.f, 0.f, 0.f);
    }
}

__device__ __forceinline__ void storeA(const float4* areg, float* Af, int buf, int tid) {
    float* base = Af + buf * A_BUF_WORDS;
#pragma unroll
    for (int t = 0; t < 4; t++) {
        int idx = tid + t * THREADS;
        int row = idx >> 3;
        int kin = (idx & 7) << 2;
        int mt = row >> 4, rr = row & 15;
        float vv[4] = {areg[t].x, areg[t].y, areg[t].z, areg[t].w};
#pragma unroll
        for (int j = 0; j < 4; j++) {
            int kk = kin + j;               // 0..31 within BK
            int ks = kk >> 3;
            int col = kk & 7;
            int ln = ((rr & 7) << 2) | (col & 3);
            int r = (rr >> 3) | ((col >> 2) << 1);
            base[(mt * 4 + ks) * A_STRIDE + ln * 4 + r] =
                __uint_as_float(cvt_rna_tf32(vv[j]));
        }
    }
}

__global__ void __launch_bounds__(THREADS, 1)
mm_kernel(const float* __restrict__ x, const void* __restrict__ batch_raw,
          const float* __restrict__ H, unsigned* __restrict__ outu) {
    extern __shared__ float sm[];
    float* Bf = sm;
    float* Af = sm + SM_A_OFF;
    int* segs = (int*)(sm + SM_SEG_OFF);
    int* p_is64 = (int*)(sm + SM_IS64_OFF);

    const int tid = threadIdx.x;
    const int wid = tid >> 5, lane = tid & 31;
    const int wm = wid >> 1, wn = wid & 1;   // 4 (m) x 2 (n) warp grid

    // batch dtype: int64 -> int32 word[NODES-1] is a hi-word == 0;
    // int32 -> it's the max sorted segment id (511 w.h.p., nonzero).
    if (tid == 0) *p_is64 = (((const int*)batch_raw)[NODES - 1] == 0);

    // Stage ALL of H once: cvt.rna -> tf32, paired-fragment layout.
    // Word index for B[n][k]: pair p=n>>4, half=(n>>3)&1, ksg=k>>3,
    //   lane=((n&7)<<2)|(k&3), slot=(k>>2)&1
    //   -> p*4224 + ksg*132 + lane*4 + half*2 + slot
    for (int i = tid; i < (NH * FDIM) / 4; i += THREADS) {
        int base = i * 4;
        int n = base >> 8;          // FDIM = 256
        int k = base & 255;
        float4 v = ((const float4*)H)[i];
        float vv[4] = {v.x, v.y, v.z, v.w};
        int p = n >> 4, half = (n >> 3) & 1;
#pragma unroll
        for (int j = 0; j < 4; j++) {
            int kk = k + j;
            int ksg = kk >> 3;
            int ln = ((n & 7) << 2) | (kk & 3);
            int slot = (kk >> 2) & 1;
            Bf[p * B_PAIR_STRIDE + ksg * B_KS_STRIDE + ln * 4 + half * 2 + slot] =
                __uint_as_float(cvt_rna_tf32(vv[j]));
        }
    }
    __syncthreads();
    const int is64 = *p_is64;

    // ---------------- persistent tile loop ----------------
    for (int t = blockIdx.x; t < NTILES; t += gridDim.x) {
        const int m0 = t * BM;

        // segment ids for this tile's rows (safe: everyone past previous
        // epilogue via the sync that ended the previous iteration)
        if (tid < BM) {
            int m = m0 + tid, s = -1;
            if (m < NODES)
                s = is64 ? (int)((const long long*)batch_raw)[m]
                         : ((const int*)batch_raw)[m];
            segs[tid] = s;
        }

        float acc[2][8][4];
#pragma unroll
        for (int i = 0; i < 2; i++)
#pragma unroll
            for (int j = 0; j < 8; j++)
#pragma unroll
                for (int r = 0; r < 4; r++) acc[i][j][r] = 0.f;

        // prologue: first A slab
        float4 areg[4];
        loadA(areg, x, m0, 0, tid);
        storeA(areg, Af, 0, tid);
        __syncthreads();

#pragma unroll 1
        for (int bk = 0; bk < NBK; bk++) {
            float4 nreg[4];
            if (bk + 1 < NBK) loadA(nreg, x, m0, (bk + 1) * BK, tid);

            const float* Ab = Af + (bk & 1) * A_BUF_WORDS;
#pragma unroll
            for (int ks = 0; ks < 4; ks++) {
                int ksg = bk * 4 + ks;
                unsigned a[2][4], b[8][2];
#pragma unroll
                for (int i = 0; i < 2; i++) {
                    int mt = wm * 2 + i;
                    float4 av = *(const float4*)(Ab + (mt * 4 + ks) * A_STRIDE + lane * 4);
                    a[i][0] = __float_as_uint(av.x); a[i][1] = __float_as_uint(av.y);
                    a[i][2] = __float_as_uint(av.z); a[i][3] = __float_as_uint(av.w);
                }
#pragma unroll
                for (int q = 0; q < 4; q++) {          // n-tile pairs
                    int p = wn * 4 + q;
                    float4 bv = *(const float4*)(Bf + p * B_PAIR_STRIDE +
                                                 ksg * B_KS_STRIDE + lane * 4);
                    b[2 * q][0]     = __float_as_uint(bv.x);
                    b[2 * q][1]     = __float_as_uint(bv.y);
                    b[2 * q + 1][0] = __float_as_uint(bv.z);
                    b[2 * q + 1][1] = __float_as_uint(bv.w);
                }
#pragma unroll
                for (int i = 0; i < 2; i++)
#pragma unroll
                    for (int j = 0; j < 8; j++)
                        mma8(acc[i][j], a[i], b[j]);
            }

            if (bk + 1 < NBK) {
                storeA(nreg, Af, (bk + 1) & 1, tid);
                __syncthreads();
            }
        }

        // ---- fused segment-min epilogue ----
        bool full = (m0 + BM) <= NODES;
        int segFirst = segs[0];
        bool fast = full && (segFirst == segs[BM - 1]) && (segFirst >= 0);

        if (fast) {
            // one segment: shuffle-reduce column mins, 1 atomic per (col, m-warp)
#pragma unroll
            for (int j = 0; j < 8; j++) {
                float v0 = fminf(fminf(acc[0][j][0], acc[0][j][2]),
                                 fminf(acc[1][j][0], acc[1][j][2]));
                float v1 = fminf(fminf(acc[0][j][1], acc[0][j][3]),
                                 fminf(acc[1][j][1], acc[1][j][3]));
#pragma unroll
                for (int off = 4; off < 32; off <<= 1) {
                    v0 = fminf(v0, __shfl_xor_sync(0xffffffffu, v0, off));
                    v1 = fminf(v1, __shfl_xor_sync(0xffffffffu, v1, off));
                }
                if (lane < 4) {
                    int col = wn * 64 + j * 8 + lane * 2;
                    atomicMin(&outu[segFirst * NH + col],     fenc(v0));
                    atomicMin(&outu[segFirst * NH + col + 1], fenc(v1));
                }
            }
        } else {
            // boundary / tail tile: per-element atomicMin
#pragma unroll
            for (int i = 0; i < 2; i++) {
                int rbase = wm * 32 + i * 16 + (lane >> 2);
#pragma unroll
                for (int j = 0; j < 8; j++) {
                    int col = wn * 64 + j * 8 + ((lane & 3) << 1);
#pragma unroll
                    for (int h = 0; h < 2; h++) {
                        int rl = rbase + h * 8;
                        if (m0 + rl < NODES) {
                            int s = segs[rl];
                            atomicMin(&outu[s * NH + col],     fenc(acc[i][j][h * 2 + 0]));
                            atomicMin(&outu[s * NH + col + 1], fenc(acc[i][j][h * 2 + 1]));
                        }
                    }
                }
            }
        }

        __syncthreads();   // protect segs + A buffers for the next iteration
    }
}

extern "C" void kernel_launch(void* const* d_in, const int* in_sizes, int n_in,
                              void* d_out, int out_size) {
    const float* x = nullptr;
    const void* batch = nullptr;
    const float* H = nullptr;
    for (int i = 0; i < n_in; i++) {
        int s = in_sizes[i];
        if (s == NODES * FDIM) x = (const float*)d_in[i];
        else if (s == NODES) batch = d_in[i];
        else if (s == NH * FDIM) H = (const float*)d_in[i];
    }
    unsigned* outu = (unsigned*)d_out;

    int nsm = 148;
    cudaDeviceGetAttribute(&nsm, cudaDevAttrMultiProcessorCount, 0);
    cudaFuncSetAttribute(mm_kernel, cudaFuncAttributeMaxDynamicSharedMemorySize, SMEM_BYTES);

    init_kernel<<<(NSEG * NH + 255) / 256, 256>>>(outu);
    mm_kernel<<<nsm, THREADS, SMEM_BYTES>>>(x, batch, H, outu);
    decode_kernel<<<(NSEG * NH + 255) / 256, 256>>>((float*)d_out);
}

// round 10
// speedup vs baseline: 2.1130x; 1.4601x over previous
#include <cuda_runtime.h>
#include <cuda_fp16.h>
#include <cstdint>

// MinHashSketch: sketch[s][h] = min over nodes m in segment s of dot(x[m], H[h]),
// empty segments -> 0.  x:[500000,256] f32, batch:[500000] i64/i32 (detected),
// H:[128,256] f32, out:[512,128] f32.
//
// Persistent mma.sync m16n8k16 FP16 GEMM (cvt.rn inputs; fp16 mantissa == tf32
// mantissa -> same ~1e-4 err, half the HMMA instructions), H staged in fp16
// fragment layout ONCE per CTA, fused segment-min epilogue with
// order-preserving uint encoding + atomicMin.

#define NODES 500000
#define FDIM 256
#define NH   128
#define NSEG 512

#define BM   128
#define BK   64
#define NBK  (FDIM / BK)        // 4 chunks
#define KSPC (BK / 16)          // 4 ksteps (k16) per chunk
#define NKS  (FDIM / 16)        // 16 global ksteps
#define THREADS 256
#define NTILES ((NODES + BM - 1) / BM)   // 3907

// Shared layout (b32 words). Fragment-ready fp16 (2 halves per word):
//  Bf: 8 nt-pairs * 16 ks * 132 = 16896 words (paired layout -> LDS.128)
//  Af: 2 bufs * (8 mt * 4 ks) * 132 = 8448 words
#define A_STRIDE      132
#define A_BUF_WORDS   (32 * A_STRIDE)        // 4224
#define B_KS_STRIDE   132
#define B_PAIR_STRIDE (NKS * B_KS_STRIDE)    // 2112
#define SM_B_WORDS    (8 * B_PAIR_STRIDE)    // 16896
#define SM_A_OFF      SM_B_WORDS
#define SM_SEG_OFF    (SM_A_OFF + 2 * A_BUF_WORDS)   // 25344
#define SM_IS64_OFF   (SM_SEG_OFF + 128)
#define SMEM_BYTES    ((SM_IS64_OFF + 4) * 4)        // ~102 KB

__device__ __forceinline__ unsigned fenc(float f) {
    unsigned u = __float_as_uint(f);
    return (u & 0x80000000u) ? ~u : (u | 0x80000000u);
}

__device__ __forceinline__ unsigned packh2(float lo, float hi) {
    __half2 h = __floats2half2_rn(lo, hi);   // .x = lo half (low 16 bits)
    return *reinterpret_cast<unsigned*>(&h);
}

__device__ __forceinline__ void mma16(float* c, const unsigned* a, const unsigned* b) {
    asm volatile(
        "mma.sync.aligned.m16n8k16.row.col.f32.f16.f16.f32 "
        "{%0,%1,%2,%3}, {%4,%5,%6,%7}, {%8,%9}, {%0,%1,%2,%3};"
        : "+f"(c[0]), "+f"(c[1]), "+f"(c[2]), "+f"(c[3])
        : "r"(a[0]), "r"(a[1]), "r"(a[2]), "r"(a[3]), "r"(b[0]), "r"(b[1]));
}

__global__ void init_kernel(unsigned* outu) {
    int i = blockIdx.x * blockDim.x + threadIdx.x;
    if (i < NSEG * NH) outu[i] = 0xFFFFFFFFu;
}

__global__ void decode_kernel(float* out) {
    int i = blockIdx.x * blockDim.x + threadIdx.x;
    if (i < NSEG * NH) {
        unsigned u = __float_as_uint(out[i]);
        float f;
        if (u == 0xFFFFFFFFu) f = 0.0f;   // empty segment -> 0
        else f = (u & 0x80000000u) ? __uint_as_float(u ^ 0x80000000u) : __uint_as_float(~u);
        out[i] = f;
    }
}

// ---- A chunk: global [128 x 64] f32 -> fp16 fragment smem ----
// m16n8k16 A frag (row-major): thread lane g=lane>>2, t=lane&3 holds
//  a0={A[g][2t],A[g][2t+1]} a1={A[g+8][..]} a2={A[g][2t+8],..} a3={A[g+8][2t+8],..}
// word addr: (mt*4+ks)*A_STRIDE + lane*4 + reg, reg=(rr>>3)+2*(kkl>>3)
__device__ __forceinline__ void loadA(float4* areg, const float* __restrict__ x,
                                      int m0, int k0, int tid) {
#pragma unroll
    for (int t = 0; t < 8; t++) {
        int idx = tid + t * THREADS;        // float4 index in 128x64 tile
        int row = idx >> 4;
        int kin = (idx & 15) << 2;
        int m = m0 + row;
        areg[t] = (m < NODES)
            ? *(const float4*)(x + (size_t)m * FDIM + k0 + kin)
            : make_float4(0.f, 0.f, 0.f, 0.f);
    }
}

__device__ __forceinline__ void storeA(const float4* areg, unsigned* Af, int buf, int tid) {
    unsigned* base = Af + buf * A_BUF_WORDS;
#pragma unroll
    for (int t = 0; t < 8; t++) {
        int idx = tid + t * THREADS;
        int row = idx >> 4;
        int kin = (idx & 15) << 2;          // 0..60, step 4
        int mt = row >> 4, rr = row & 15;
        int ks = kin >> 4, kkl = kin & 15;
        int reg = (rr >> 3) + ((kkl >> 3) << 1);
        int lane0 = ((rr & 7) << 2) | ((kkl >> 1) & 3);
        unsigned* p = base + (mt * 4 + ks) * A_STRIDE + lane0 * 4 + reg;
        p[0] = packh2(areg[t].x, areg[t].y);   // k = kin, kin+1
        p[4] = packh2(areg[t].z, areg[t].w);   // k = kin+2, kin+3 (lane0+1)
    }
}

__global__ void __launch_bounds__(THREADS, 1)
mm_kernel(const float* __restrict__ x, const void* __restrict__ batch_raw,
          const float* __restrict__ H, unsigned* __restrict__ outu) {
    extern __shared__ float sm[];
    unsigned* Bfu = (unsigned*)sm;
    unsigned* Afu = (unsigned*)(sm + SM_A_OFF);
    int* segs = (int*)(sm + SM_SEG_OFF);
    int* p_is64 = (int*)(sm + SM_IS64_OFF);

    const int tid = threadIdx.x;
    const int wid = tid >> 5, lane = tid & 31;
    const int wm = wid >> 1, wn = wid & 1;   // 4 (m) x 2 (n) warp grid

    // batch dtype: int64 -> int32 word[NODES-1] is a hi-word == 0;
    // int32 -> it's the max sorted segment id (nonzero w.h.p.).
    if (tid == 0) *p_is64 = (((const int*)batch_raw)[NODES - 1] == 0);

    // Stage ALL of H once: f32 -> fp16 pairs, paired-fragment layout.
    // m16n8k16 B frag (col): n = lane>>2, b0={B[n][2t],B[n][2t+1]}, b1={..+8}
    // word = p*B_PAIR_STRIDE + ks*B_KS_STRIDE + lane0*4 + half*2 + reg
    for (int i = tid; i < (NH * FDIM) / 4; i += THREADS) {
        int n = i >> 6;                 // 64 float4 per H row
        int k = (i & 63) << 2;
        float4 v = ((const float4*)H)[i];
        int pp = n >> 4, half = (n >> 3) & 1, ncol = n & 7;
        int ks = k >> 4, kkl = k & 15;
        int lane0 = (ncol << 2) | ((kkl >> 1) & 3);
        int reg = kkl >> 3;
        unsigned* b = Bfu + pp * B_PAIR_STRIDE + ks * B_KS_STRIDE + (half << 1);
        b[lane0 * 4 + reg]       = packh2(v.x, v.y);
        b[(lane0 + 1) * 4 + reg] = packh2(v.z, v.w);
    }
    __syncthreads();
    const int is64 = *p_is64;

    // ---------------- persistent tile loop ----------------
    for (int t = blockIdx.x; t < NTILES; t += gridDim.x) {
        const int m0 = t * BM;

        if (tid < BM) {
            int m = m0 + tid, s = -1;
            if (m < NODES)
                s = is64 ? (int)((const long long*)batch_raw)[m]
                         : ((const int*)batch_raw)[m];
            segs[tid] = s;
        }

        float acc[2][8][4];
#pragma unroll
        for (int i = 0; i < 2; i++)
#pragma unroll
            for (int j = 0; j < 8; j++)
#pragma unroll
                for (int r = 0; r < 4; r++) acc[i][j][r] = 0.f;

        // prologue: first A chunk
        float4 areg[8];
        loadA(areg, x, m0, 0, tid);
        storeA(areg, Afu, 0, tid);
        __syncthreads();

#pragma unroll 1
        for (int bk = 0; bk < NBK; bk++) {
            float4 nreg[8];
            if (bk + 1 < NBK) loadA(nreg, x, m0, (bk + 1) * BK, tid);

            const unsigned* Ab = Afu + (bk & 1) * A_BUF_WORDS;
#pragma unroll
            for (int ks = 0; ks < KSPC; ks++) {
                int ksg = bk * KSPC + ks;
                unsigned a[2][4], b[8][2];
#pragma unroll
                for (int i = 0; i < 2; i++) {
                    int mt = wm * 2 + i;
                    uint4 av = *(const uint4*)(Ab + (mt * 4 + ks) * A_STRIDE + lane * 4);
                    a[i][0] = av.x; a[i][1] = av.y; a[i][2] = av.z; a[i][3] = av.w;
                }
#pragma unroll
                for (int q = 0; q < 4; q++) {          // n-tile pairs
                    int pp = wn * 4 + q;
                    uint4 bv = *(const uint4*)(Bfu + pp * B_PAIR_STRIDE +
                                               ksg * B_KS_STRIDE + lane * 4);
                    b[2 * q][0]     = bv.x;
                    b[2 * q][1]     = bv.y;
                    b[2 * q + 1][0] = bv.z;
                    b[2 * q + 1][1] = bv.w;
                }
#pragma unroll
                for (int i = 0; i < 2; i++)
#pragma unroll
                    for (int j = 0; j < 8; j++)
                        mma16(acc[i][j], a[i], b[j]);
            }

            if (bk + 1 < NBK) {
                storeA(nreg, Afu, (bk + 1) & 1, tid);
                __syncthreads();
            }
        }

        // ---- fused segment-min epilogue (C frag layout == tf32 version) ----
        bool full = (m0 + BM) <= NODES;
        int segFirst = segs[0];
        bool fast = full && (segFirst == segs[BM - 1]) && (segFirst >= 0);

        if (fast) {
#pragma unroll
            for (int j = 0; j < 8; j++) {
                float v0 = fminf(fminf(acc[0][j][0], acc[0][j][2]),
                                 fminf(acc[1][j][0], acc[1][j][2]));
                float v1 = fminf(fminf(acc[0][j][1], acc[0][j][3]),
                                 fminf(acc[1][j][1], acc[1][j][3]));
#pragma unroll
                for (int off = 4; off < 32; off <<= 1) {
                    v0 = fminf(v0, __shfl_xor_sync(0xffffffffu, v0, off));
                    v1 = fminf(v1, __shfl_xor_sync(0xffffffffu, v1, off));
                }
                if (lane < 4) {
                    int col = wn * 64 + j * 8 + lane * 2;
                    atomicMin(&outu[segFirst * NH + col],     fenc(v0));
                    atomicMin(&outu[segFirst * NH + col + 1], fenc(v1));
                }
            }
        } else {
#pragma unroll
            for (int i = 0; i < 2; i++) {
                int rbase = wm * 32 + i * 16 + (lane >> 2);
#pragma unroll
                for (int j = 0; j < 8; j++) {
                    int col = wn * 64 + j * 8 + ((lane & 3) << 1);
#pragma unroll
                    for (int h = 0; h < 2; h++) {
                        int rl = rbase + h * 8;
                        if (m0 + rl < NODES) {
                            int s = segs[rl];
                            atomicMin(&outu[s * NH + col],     fenc(acc[i][j][h * 2 + 0]));
                            atomicMin(&outu[s * NH + col + 1], fenc(acc[i][j][h * 2 + 1]));
                        }
                    }
                }
            }
        }

        __syncthreads();   // protect segs + A buffers for the next iteration
    }
}

extern "C" void kernel_launch(void* const* d_in, const int* in_sizes, int n_in,
                              void* d_out, int out_size) {
    const float* x = nullptr;
    const void* batch = nullptr;
    const float* H = nullptr;
    for (int i = 0; i < n_in; i++) {
        int s = in_sizes[i];
        if (s == NODES * FDIM) x = (const float*)d_in[i];
        else if (s == NODES) batch = d_in[i];
        else if (s == NH * FDIM) H = (const float*)d_in[i];
    }
    unsigned* outu = (unsigned*)d_out;

    int nsm = 148;
    cudaDeviceGetAttribute(&nsm, cudaDevAttrMultiProcessorCount, 0);
    cudaFuncSetAttribute(mm_kernel, cudaFuncAttributeMaxDynamicSharedMemorySize, SMEM_BYTES);

    init_kernel<<<(NSEG * NH + 255) / 256, 256>>>(outu);
    mm_kernel<<<nsm, THREADS, SMEM_BYTES>>>(x, batch, H, outu);
    decode_kernel<<<(NSEG * NH + 255) / 256, 256>>>((float*)d_out);
}